// round 7
// baseline (speedup 1.0000x reference)
#include <cuda_runtime.h>
#include <cuda_bf16.h>
#include <stdint.h>

// ============================================================================
// GumbelTopK R7: 16-bit key store + exact resolve of threshold bin.
//  A: score -> key16 (32MB) + smem hist of top 12 bits        [160MB]
//  select1: pick 12-bit bin holding rank k
//  collect: indices of elements in that bin (~2.4%), block-aggregated [32MB]
//  resolve: recompute exact 32-bit keys for candidates, 20-bit histogram
//  select2: exact threshold T + rank r; tie indices -> cutoff
//  final: stream key16 + u2; ambiguous (top12==prefix) recompute exactly [249MB]
// ============================================================================

#define N_MAX   (1u << 24)       // 4096*4096
#define H1_BINS 4096             // top 12 bits
#define H2_BINS (1u << 20)       // low 20 bits of exact key
#define EPSF    1e-8f

__device__ unsigned short g_key16[N_MAX];
__device__ int            g_cand_idx[N_MAX];
__device__ unsigned int   g_cand_key[N_MAX];
__device__ int            g_tie_idx[N_MAX];
__device__ unsigned int   g_hist1[H1_BINS];
__device__ unsigned int   g_hist2[H2_BINS];
__device__ unsigned int   g_csum2[1024];
__device__ unsigned int   g_cand_cnt;
__device__ unsigned int   g_tie_cnt;
__device__ unsigned int   g_prefix12;
__device__ unsigned int   g_k1;
__device__ unsigned int   g_T;
__device__ unsigned int   g_r;
__device__ int            g_cutoff;

__device__ __forceinline__ float gum(float u) {
    return -logf(-logf(u + EPSF) + EPSF);
}

__device__ __forceinline__ unsigned int f2key(float f) {
    unsigned int b = __float_as_uint(f);
    return (b & 0x80000000u) ? ~b : (b | 0x80000000u);
}

// ---------------------------------------------------------------------------
__global__ void reset_k() {
    int stride = gridDim.x * blockDim.x;
    for (unsigned int i = blockIdx.x * blockDim.x + threadIdx.x; i < H2_BINS; i += stride)
        g_hist2[i] = 0;
    unsigned int t = blockIdx.x * blockDim.x + threadIdx.x;
    if (t < H1_BINS) g_hist1[t] = 0;
    if (t == 0) { g_cand_cnt = 0; g_tie_cnt = 0; }
}

// ---------------------------------------------------------------------------
// pass A: score -> key16 store + 12-bit smem histogram (2-way replicated)
// ---------------------------------------------------------------------------
__global__ void __launch_bounds__(256) score16_k(
        const float* __restrict__ logits,
        const float* __restrict__ u1,
        const int* __restrict__ training, int n4) {
    __shared__ unsigned int sh[2 * H1_BINS];     // 32 KB
    for (int i = threadIdx.x; i < 2 * H1_BINS; i += blockDim.x) sh[i] = 0;
    __syncthreads();
    unsigned int* mysh = sh + ((threadIdx.x >> 5) & 1) * H1_BINS;
    const int tr = *training;
    const int stride = gridDim.x * blockDim.x;
    int i = blockIdx.x * blockDim.x + threadIdx.x;
    for (; i + stride < n4; i += 2 * stride) {
        float4 l0 = __ldcs((const float4*)logits + i);
        float4 u0 = __ldcs((const float4*)u1 + i);
        float4 l1 = __ldcs((const float4*)logits + i + stride);
        float4 u1v = __ldcs((const float4*)u1 + i + stride);
        unsigned int a0 = f2key(tr ? (l0.x + gum(u0.x)) : l0.x);
        unsigned int a1 = f2key(tr ? (l0.y + gum(u0.y)) : l0.y);
        unsigned int a2 = f2key(tr ? (l0.z + gum(u0.z)) : l0.z);
        unsigned int a3 = f2key(tr ? (l0.w + gum(u0.w)) : l0.w);
        unsigned int b0 = f2key(tr ? (l1.x + gum(u1v.x)) : l1.x);
        unsigned int b1 = f2key(tr ? (l1.y + gum(u1v.y)) : l1.y);
        unsigned int b2 = f2key(tr ? (l1.z + gum(u1v.z)) : l1.z);
        unsigned int b3 = f2key(tr ? (l1.w + gum(u1v.w)) : l1.w);
        uint2 p0, p1;
        p0.x = (a0 >> 16) | (a1 & 0xFFFF0000u);
        p0.y = (a2 >> 16) | (a3 & 0xFFFF0000u);
        p1.x = (b0 >> 16) | (b1 & 0xFFFF0000u);
        p1.y = (b2 >> 16) | (b3 & 0xFFFF0000u);
        ((uint2*)g_key16)[i] = p0;
        ((uint2*)g_key16)[i + stride] = p1;
        atomicAdd(&mysh[a0 >> 20], 1u);
        atomicAdd(&mysh[a1 >> 20], 1u);
        atomicAdd(&mysh[a2 >> 20], 1u);
        atomicAdd(&mysh[a3 >> 20], 1u);
        atomicAdd(&mysh[b0 >> 20], 1u);
        atomicAdd(&mysh[b1 >> 20], 1u);
        atomicAdd(&mysh[b2 >> 20], 1u);
        atomicAdd(&mysh[b3 >> 20], 1u);
    }
    for (; i < n4; i += stride) {
        float4 l = __ldcs((const float4*)logits + i);
        float4 u = __ldcs((const float4*)u1 + i);
        unsigned int a0 = f2key(tr ? (l.x + gum(u.x)) : l.x);
        unsigned int a1 = f2key(tr ? (l.y + gum(u.y)) : l.y);
        unsigned int a2 = f2key(tr ? (l.z + gum(u.z)) : l.z);
        unsigned int a3 = f2key(tr ? (l.w + gum(u.w)) : l.w);
        uint2 p;
        p.x = (a0 >> 16) | (a1 & 0xFFFF0000u);
        p.y = (a2 >> 16) | (a3 & 0xFFFF0000u);
        ((uint2*)g_key16)[i] = p;
        atomicAdd(&mysh[a0 >> 20], 1u);
        atomicAdd(&mysh[a1 >> 20], 1u);
        atomicAdd(&mysh[a2 >> 20], 1u);
        atomicAdd(&mysh[a3 >> 20], 1u);
    }
    __syncthreads();
    for (int b = threadIdx.x; b < H1_BINS; b += blockDim.x) {
        unsigned int c = sh[b] + sh[b + H1_BINS];
        if (c) atomicAdd(&g_hist1[b], c);
    }
}

// ---------------------------------------------------------------------------
__device__ __forceinline__ unsigned int block_incl_scan(unsigned int v, unsigned int* sh) {
    int t = threadIdx.x;
    sh[t] = v;
    __syncthreads();
    for (int off = 1; off < blockDim.x; off <<= 1) {
        unsigned int add = (t >= off) ? sh[t - off] : 0u;
        __syncthreads();
        sh[t] += add;
        __syncthreads();
    }
    return sh[t];
}

// select level 1: 12-bit bin holding rank-k (descending)
__global__ void select1_k(const int* __restrict__ kp) {
    __shared__ unsigned int sh[1024];
    const unsigned int k = (unsigned int)(*kp);
    int t = threadIdx.x;
    unsigned int c[4], s = 0;
#pragma unroll
    for (int j = 0; j < 4; j++) { c[j] = g_hist1[4095 - (4 * t + j)]; s += c[j]; }
    unsigned int incl = block_incl_scan(s, sh);
    unsigned int excl = incl - s;
    if (excl < k && k <= incl) {
        unsigned int cum = excl;
#pragma unroll
        for (int j = 0; j < 4; j++) {
            if (cum + c[j] >= k) { g_prefix12 = 4095 - (4 * t + j); g_k1 = k - cum; break; }
            cum += c[j];
        }
    }
}

// ---------------------------------------------------------------------------
// collect: indices whose top-12 key bits == prefix12, block-aggregated append.
// ---------------------------------------------------------------------------
#define COLLECT_CAP 8192
__global__ void __launch_bounds__(256) collect_k(int n4) {
    __shared__ int s_buf[COLLECT_CAP];     // 32 KB
    __shared__ int s_cnt;
    __shared__ unsigned int s_base;
    if (threadIdx.x == 0) s_cnt = 0;
    __syncthreads();
    const unsigned int pfx = g_prefix12;
    const int stride = gridDim.x * blockDim.x;
    for (int i = blockIdx.x * blockDim.x + threadIdx.x; i < n4; i += stride) {
        uint2 p = __ldcs((const uint2*)g_key16 + i);
        unsigned int k0 = p.x & 0xFFFFu, k1 = p.x >> 16;
        unsigned int k2 = p.y & 0xFFFFu, k3 = p.y >> 16;
        if ((k0 >> 4) == pfx) { int q = atomicAdd(&s_cnt, 1); if (q < COLLECT_CAP) s_buf[q] = 4 * i + 0; }
        if ((k1 >> 4) == pfx) { int q = atomicAdd(&s_cnt, 1); if (q < COLLECT_CAP) s_buf[q] = 4 * i + 1; }
        if ((k2 >> 4) == pfx) { int q = atomicAdd(&s_cnt, 1); if (q < COLLECT_CAP) s_buf[q] = 4 * i + 2; }
        if ((k3 >> 4) == pfx) { int q = atomicAdd(&s_cnt, 1); if (q < COLLECT_CAP) s_buf[q] = 4 * i + 3; }
    }
    __syncthreads();
    int cnt = s_cnt;
    if (cnt > COLLECT_CAP) cnt = COLLECT_CAP;
    if (threadIdx.x == 0) s_base = atomicAdd(&g_cand_cnt, (unsigned int)cnt);
    __syncthreads();
    unsigned int base = s_base;
    for (int j = threadIdx.x; j < cnt; j += blockDim.x)
        g_cand_idx[base + j] = s_buf[j];
}

// ---------------------------------------------------------------------------
// resolve: recompute exact 32-bit keys for candidates, histogram low 20 bits.
// ---------------------------------------------------------------------------
__global__ void __launch_bounds__(256) resolve_k(
        const float* __restrict__ logits,
        const float* __restrict__ u1,
        const int* __restrict__ training) {
    const int tr = *training;
    const unsigned int m = g_cand_cnt;
    const unsigned int stride = gridDim.x * blockDim.x;
    for (unsigned int i = blockIdx.x * blockDim.x + threadIdx.x; i < m; i += stride) {
        int idx = g_cand_idx[i];
        float l = __ldg(&logits[idx]);
        float u = __ldg(&u1[idx]);
        unsigned int key = f2key(tr ? (l + gum(u)) : l);
        g_cand_key[i] = key;
        atomicAdd(&g_hist2[key & 0xFFFFFu], 1u);
    }
}

// chunk sums of hist2 (1024 chunks of 1024 bins)
__global__ void chunksum2_k() {
    __shared__ unsigned int sh[256];
    int b = blockIdx.x;
    unsigned int s = 0;
    for (int j = threadIdx.x; j < 1024; j += 256) s += g_hist2[b * 1024 + j];
    sh[threadIdx.x] = s;
    __syncthreads();
    for (int off = 128; off > 0; off >>= 1) {
        if (threadIdx.x < off) sh[threadIdx.x] += sh[threadIdx.x + off];
        __syncthreads();
    }
    if (threadIdx.x == 0) g_csum2[b] = sh[0];
}

// select level 2: exact threshold key T and r = #(==T) to include
__global__ void select2_k() {
    __shared__ unsigned int sh[1024];
    __shared__ unsigned int s_chunk, s_k2;
    int t = threadIdx.x;
    const unsigned int k1 = g_k1;
    unsigned int s = g_csum2[1023 - t];
    unsigned int incl = block_incl_scan(s, sh);
    unsigned int excl = incl - s;
    if (excl < k1 && k1 <= incl) { s_chunk = 1023 - t; s_k2 = k1 - excl; }
    __syncthreads();
    const unsigned int a = s_chunk;
    const unsigned int k2 = s_k2;
    unsigned int bin = a * 1024 + 1023 - t;
    unsigned int cb = g_hist2[bin];
    __syncthreads();
    unsigned int incl2 = block_incl_scan(cb, sh);
    unsigned int excl2 = incl2 - cb;
    if (excl2 < k2 && k2 <= incl2) {
        g_T = (g_prefix12 << 20) | bin;
        g_r = k2 - excl2;
    }
}

// ---------------------------------------------------------------------------
// ties: candidates with key == T (tiny); then cutoff = r-th smallest index
// ---------------------------------------------------------------------------
__global__ void tie_collect_k() {
    const unsigned int T = g_T;
    const unsigned int m = g_cand_cnt;
    const unsigned int stride = gridDim.x * blockDim.x;
    for (unsigned int i = blockIdx.x * blockDim.x + threadIdx.x; i < m; i += stride) {
        if (g_cand_key[i] == T) {
            unsigned int p = atomicAdd(&g_tie_cnt, 1u);
            g_tie_idx[p] = g_cand_idx[i];
        }
    }
}

__global__ void cutoff_k(int n) {
    __shared__ int s_cnt;
    unsigned int m = g_tie_cnt;
    const unsigned int r = g_r;
    if (r == 0 || m == 0) { if (threadIdx.x == 0) g_cutoff = -1; return; }
    int lo = 0, hi = n - 1;
    while (lo < hi) {
        int mid = lo + (hi - lo) / 2;
        if (threadIdx.x == 0) s_cnt = 0;
        __syncthreads();
        int c = 0;
        for (unsigned int j = threadIdx.x; j < m; j += blockDim.x)
            if (g_tie_idx[j] <= mid) c++;
        if (c) atomicAdd(&s_cnt, c);
        __syncthreads();
        if (s_cnt >= (int)r) hi = mid; else lo = mid + 1;
        __syncthreads();
    }
    if (threadIdx.x == 0) g_cutoff = lo;
}

// ---------------------------------------------------------------------------
// final: stream key16 + u2 -> out. top12 > pfx: in; < pfx: out;
// == pfx: recompute exact key (sparse gather) and compare with T / cutoff.
// ---------------------------------------------------------------------------
__device__ __forceinline__ float out_elem16(
        unsigned int key16, int idx, float v0, float v1,
        const float* __restrict__ logits, const float* __restrict__ u1,
        unsigned int pfx, unsigned int T, int cutoff, int tr) {
    unsigned int top12 = key16 >> 4;
    float m;
    if (top12 > pfx) m = 1.0f;
    else if (top12 < pfx) m = 0.0f;
    else {
        float l = __ldg(&logits[idx]);
        float u = __ldg(&u1[idx]);
        unsigned int key = f2key(tr ? (l + gum(u)) : l);
        m = (key > T || (key == T && idx <= cutoff)) ? 1.0f : 0.0f;
    }
    if (!tr) return m;
    return (m + gum(v1) > gum(v0)) ? 1.0f : 0.0f;
}

__global__ void __launch_bounds__(256) final_k(
        const float* __restrict__ u2,
        const float* __restrict__ logits,
        const float* __restrict__ u1,
        const int* __restrict__ training,
        float* __restrict__ out, int n4) {
    const unsigned int pfx = g_prefix12;
    const unsigned int T = g_T;
    const int cutoff = g_cutoff;
    const int tr = *training;
    const int stride = gridDim.x * blockDim.x;
    int i = blockIdx.x * blockDim.x + threadIdx.x;
    for (; i + stride < n4; i += 2 * stride) {
        uint2 p0 = ((const uint2*)g_key16)[i];
        float4 a0 = __ldcs((const float4*)u2 + 2 * i);
        float4 b0 = __ldcs((const float4*)u2 + 2 * i + 1);
        uint2 p1 = ((const uint2*)g_key16)[i + stride];
        float4 a1 = __ldcs((const float4*)u2 + 2 * (i + stride));
        float4 b1 = __ldcs((const float4*)u2 + 2 * (i + stride) + 1);
        float4 o0, o1;
        o0.x = out_elem16(p0.x & 0xFFFFu, 4 * i + 0, a0.x, a0.y, logits, u1, pfx, T, cutoff, tr);
        o0.y = out_elem16(p0.x >> 16,     4 * i + 1, a0.z, a0.w, logits, u1, pfx, T, cutoff, tr);
        o0.z = out_elem16(p0.y & 0xFFFFu, 4 * i + 2, b0.x, b0.y, logits, u1, pfx, T, cutoff, tr);
        o0.w = out_elem16(p0.y >> 16,     4 * i + 3, b0.z, b0.w, logits, u1, pfx, T, cutoff, tr);
        int j = i + stride;
        o1.x = out_elem16(p1.x & 0xFFFFu, 4 * j + 0, a1.x, a1.y, logits, u1, pfx, T, cutoff, tr);
        o1.y = out_elem16(p1.x >> 16,     4 * j + 1, a1.z, a1.w, logits, u1, pfx, T, cutoff, tr);
        o1.z = out_elem16(p1.y & 0xFFFFu, 4 * j + 2, b1.x, b1.y, logits, u1, pfx, T, cutoff, tr);
        o1.w = out_elem16(p1.y >> 16,     4 * j + 3, b1.z, b1.w, logits, u1, pfx, T, cutoff, tr);
        __stcs((float4*)out + i, o0);
        __stcs((float4*)out + j, o1);
    }
    for (; i < n4; i += stride) {
        uint2 p = ((const uint2*)g_key16)[i];
        float4 a = __ldcs((const float4*)u2 + 2 * i);
        float4 b = __ldcs((const float4*)u2 + 2 * i + 1);
        float4 o;
        o.x = out_elem16(p.x & 0xFFFFu, 4 * i + 0, a.x, a.y, logits, u1, pfx, T, cutoff, tr);
        o.y = out_elem16(p.x >> 16,     4 * i + 1, a.z, a.w, logits, u1, pfx, T, cutoff, tr);
        o.z = out_elem16(p.y & 0xFFFFu, 4 * i + 2, b.x, b.y, logits, u1, pfx, T, cutoff, tr);
        o.w = out_elem16(p.y >> 16,     4 * i + 3, b.z, b.w, logits, u1, pfx, T, cutoff, tr);
        __stcs((float4*)out + i, o);
    }
}

// ---------------------------------------------------------------------------
extern "C" void kernel_launch(void* const* d_in, const int* in_sizes, int n_in,
                              void* d_out, int out_size) {
    const float* mask_logits = (const float*)d_in[0];
    const float* u1          = (const float*)d_in[1];
    const float* u2          = (const float*)d_in[2];
    const int*   kp          = (const int*)d_in[3];
    const int*   training    = (const int*)d_in[4];
    float* out = (float*)d_out;

    const int n  = in_sizes[0];
    const int n4 = n / 4;

    reset_k<<<1024, 256>>>();
    score16_k<<<2048, 256>>>(mask_logits, u1, training, n4);
    select1_k<<<1, 1024>>>(kp);
    collect_k<<<2048, 256>>>(n4);
    resolve_k<<<512, 256>>>(mask_logits, u1, training);
    chunksum2_k<<<1024, 256>>>();
    select2_k<<<1, 1024>>>();
    tie_collect_k<<<256, 256>>>();
    cutoff_k<<<1, 1024>>>(n);
    final_k<<<4096, 256>>>(u2, mask_logits, u1, training, out, n4);
}

// round 9
// speedup vs baseline: 1.0706x; 1.0706x over previous
#include <cuda_runtime.h>
#include <cuda_bf16.h>
#include <stdint.h>

// ============================================================================
// GumbelTopK R9 (= R8 resubmitted after infra flake): 16-bit key store +
// exact resolve of threshold bin.
//  A:       score -> key16 (32MB) + 12-bit smem hist            [160MB]
//  select1: pick 12-bit bin holding rank k
//  collect: indices with top12 == pfx (~2.7%), uint4 + unroll   [32MB]
//  resolve: recompute exact keys for candidates, 20-bit hist    [~30MB rnd]
//  select2: exact threshold T + rank r; ties -> index cutoff
//  final:   stream key16+u2 -> out; ambiguous = provisional 0   [224MB]
//  fixup2:  rewrite included candidates with mask=1             [~15MB rnd]
// ============================================================================

#define N_MAX    (1u << 24)      // 4096*4096
#define H1_BINS  4096            // top 12 bits
#define H2_BINS  (1u << 20)      // low 20 bits of exact key
#define CAND_CAP (1u << 22)      // 4M candidates max
#define TIE_CAP  (1u << 20)
#define EPSF     1e-8f

__device__ unsigned short g_key16[N_MAX];
__device__ int            g_cand_idx[CAND_CAP];
__device__ unsigned int   g_cand_key[CAND_CAP];
__device__ int            g_tie_idx[TIE_CAP];
__device__ unsigned int   g_hist1[H1_BINS];
__device__ unsigned int   g_hist2[H2_BINS];
__device__ unsigned int   g_csum2[1024];
__device__ unsigned int   g_cand_cnt;
__device__ unsigned int   g_tie_cnt;
__device__ unsigned int   g_prefix12;
__device__ unsigned int   g_k1;
__device__ unsigned int   g_T;
__device__ unsigned int   g_r;
__device__ int            g_cutoff;

__device__ __forceinline__ float gum(float u) {
    return -logf(-logf(u + EPSF) + EPSF);
}

__device__ __forceinline__ unsigned int f2key(float f) {
    unsigned int b = __float_as_uint(f);
    return (b & 0x80000000u) ? ~b : (b | 0x80000000u);
}

// ---------------------------------------------------------------------------
__global__ void reset_k() {
    int stride = gridDim.x * blockDim.x;
    for (unsigned int i = blockIdx.x * blockDim.x + threadIdx.x; i < H2_BINS; i += stride)
        g_hist2[i] = 0;
    unsigned int t = blockIdx.x * blockDim.x + threadIdx.x;
    if (t < H1_BINS) g_hist1[t] = 0;
    if (t == 0) { g_cand_cnt = 0; g_tie_cnt = 0; }
}

// ---------------------------------------------------------------------------
// pass A: score -> key16 store + 12-bit smem histogram (2-way replicated)
// ---------------------------------------------------------------------------
__global__ void __launch_bounds__(256) score16_k(
        const float* __restrict__ logits,
        const float* __restrict__ u1,
        const int* __restrict__ training, int n4) {
    __shared__ unsigned int sh[2 * H1_BINS];     // 32 KB
    for (int i = threadIdx.x; i < 2 * H1_BINS; i += blockDim.x) sh[i] = 0;
    __syncthreads();
    unsigned int* mysh = sh + ((threadIdx.x >> 5) & 1) * H1_BINS;
    const int tr = *training;
    const int stride = gridDim.x * blockDim.x;
    int i = blockIdx.x * blockDim.x + threadIdx.x;
    for (; i + stride < n4; i += 2 * stride) {
        float4 l0 = __ldcs((const float4*)logits + i);
        float4 u0 = __ldcs((const float4*)u1 + i);
        float4 l1 = __ldcs((const float4*)logits + i + stride);
        float4 u1v = __ldcs((const float4*)u1 + i + stride);
        unsigned int a0 = f2key(tr ? (l0.x + gum(u0.x)) : l0.x);
        unsigned int a1 = f2key(tr ? (l0.y + gum(u0.y)) : l0.y);
        unsigned int a2 = f2key(tr ? (l0.z + gum(u0.z)) : l0.z);
        unsigned int a3 = f2key(tr ? (l0.w + gum(u0.w)) : l0.w);
        unsigned int b0 = f2key(tr ? (l1.x + gum(u1v.x)) : l1.x);
        unsigned int b1 = f2key(tr ? (l1.y + gum(u1v.y)) : l1.y);
        unsigned int b2 = f2key(tr ? (l1.z + gum(u1v.z)) : l1.z);
        unsigned int b3 = f2key(tr ? (l1.w + gum(u1v.w)) : l1.w);
        uint2 p0, p1;
        p0.x = (a0 >> 16) | (a1 & 0xFFFF0000u);
        p0.y = (a2 >> 16) | (a3 & 0xFFFF0000u);
        p1.x = (b0 >> 16) | (b1 & 0xFFFF0000u);
        p1.y = (b2 >> 16) | (b3 & 0xFFFF0000u);
        ((uint2*)g_key16)[i] = p0;
        ((uint2*)g_key16)[i + stride] = p1;
        atomicAdd(&mysh[a0 >> 20], 1u);
        atomicAdd(&mysh[a1 >> 20], 1u);
        atomicAdd(&mysh[a2 >> 20], 1u);
        atomicAdd(&mysh[a3 >> 20], 1u);
        atomicAdd(&mysh[b0 >> 20], 1u);
        atomicAdd(&mysh[b1 >> 20], 1u);
        atomicAdd(&mysh[b2 >> 20], 1u);
        atomicAdd(&mysh[b3 >> 20], 1u);
    }
    for (; i < n4; i += stride) {
        float4 l = __ldcs((const float4*)logits + i);
        float4 u = __ldcs((const float4*)u1 + i);
        unsigned int a0 = f2key(tr ? (l.x + gum(u.x)) : l.x);
        unsigned int a1 = f2key(tr ? (l.y + gum(u.y)) : l.y);
        unsigned int a2 = f2key(tr ? (l.z + gum(u.z)) : l.z);
        unsigned int a3 = f2key(tr ? (l.w + gum(u.w)) : l.w);
        uint2 p;
        p.x = (a0 >> 16) | (a1 & 0xFFFF0000u);
        p.y = (a2 >> 16) | (a3 & 0xFFFF0000u);
        ((uint2*)g_key16)[i] = p;
        atomicAdd(&mysh[a0 >> 20], 1u);
        atomicAdd(&mysh[a1 >> 20], 1u);
        atomicAdd(&mysh[a2 >> 20], 1u);
        atomicAdd(&mysh[a3 >> 20], 1u);
    }
    __syncthreads();
    for (int b = threadIdx.x; b < H1_BINS; b += blockDim.x) {
        unsigned int c = sh[b] + sh[b + H1_BINS];
        if (c) atomicAdd(&g_hist1[b], c);
    }
}

// ---------------------------------------------------------------------------
__device__ __forceinline__ unsigned int block_incl_scan(unsigned int v, unsigned int* sh) {
    int t = threadIdx.x;
    sh[t] = v;
    __syncthreads();
    for (int off = 1; off < blockDim.x; off <<= 1) {
        unsigned int add = (t >= off) ? sh[t - off] : 0u;
        __syncthreads();
        sh[t] += add;
        __syncthreads();
    }
    return sh[t];
}

// select level 1: 12-bit bin holding rank-k (descending)
__global__ void select1_k(const int* __restrict__ kp) {
    __shared__ unsigned int sh[1024];
    const unsigned int k = (unsigned int)(*kp);
    int t = threadIdx.x;
    unsigned int c[4], s = 0;
#pragma unroll
    for (int j = 0; j < 4; j++) { c[j] = g_hist1[4095 - (4 * t + j)]; s += c[j]; }
    unsigned int incl = block_incl_scan(s, sh);
    unsigned int excl = incl - s;
    if (excl < k && k <= incl) {
        unsigned int cum = excl;
#pragma unroll
        for (int j = 0; j < 4; j++) {
            if (cum + c[j] >= k) { g_prefix12 = 4095 - (4 * t + j); g_k1 = k - cum; break; }
            cum += c[j];
        }
    }
}

// ---------------------------------------------------------------------------
// collect: indices whose top-12 bits == prefix. uint4 loads (8 keys) + 2x
// unroll = 32B in flight per thread. Block-aggregated append.
// ---------------------------------------------------------------------------
#define COLLECT_CAP 4096
__global__ void __launch_bounds__(256) collect_k(int n8) {
    __shared__ int s_buf[COLLECT_CAP];     // 16 KB
    __shared__ int s_cnt;
    __shared__ unsigned int s_base;
    if (threadIdx.x == 0) s_cnt = 0;
    __syncthreads();
    const unsigned int pfx4 = g_prefix12 << 4;   // compare against key16 & 0xFFF0
    const int stride = gridDim.x * blockDim.x;
    int i = blockIdx.x * blockDim.x + threadIdx.x;
    for (; i + stride < n8; i += 2 * stride) {
        uint4 pA = __ldcs((const uint4*)g_key16 + i);
        uint4 pB = __ldcs((const uint4*)g_key16 + i + stride);
#pragma unroll
        for (int w = 0; w < 4; w++) {
            unsigned int v = (w == 0) ? pA.x : (w == 1) ? pA.y : (w == 2) ? pA.z : pA.w;
            if ((v & 0xFFF0u) == pfx4)         { int q = atomicAdd(&s_cnt, 1); if (q < COLLECT_CAP) s_buf[q] = 8 * i + 2 * w; }
            if (((v >> 16) & 0xFFF0u) == pfx4) { int q = atomicAdd(&s_cnt, 1); if (q < COLLECT_CAP) s_buf[q] = 8 * i + 2 * w + 1; }
        }
        int ib = i + stride;
#pragma unroll
        for (int w = 0; w < 4; w++) {
            unsigned int v = (w == 0) ? pB.x : (w == 1) ? pB.y : (w == 2) ? pB.z : pB.w;
            if ((v & 0xFFF0u) == pfx4)         { int q = atomicAdd(&s_cnt, 1); if (q < COLLECT_CAP) s_buf[q] = 8 * ib + 2 * w; }
            if (((v >> 16) & 0xFFF0u) == pfx4) { int q = atomicAdd(&s_cnt, 1); if (q < COLLECT_CAP) s_buf[q] = 8 * ib + 2 * w + 1; }
        }
    }
    for (; i < n8; i += stride) {
        uint4 pA = __ldcs((const uint4*)g_key16 + i);
#pragma unroll
        for (int w = 0; w < 4; w++) {
            unsigned int v = (w == 0) ? pA.x : (w == 1) ? pA.y : (w == 2) ? pA.z : pA.w;
            if ((v & 0xFFF0u) == pfx4)         { int q = atomicAdd(&s_cnt, 1); if (q < COLLECT_CAP) s_buf[q] = 8 * i + 2 * w; }
            if (((v >> 16) & 0xFFF0u) == pfx4) { int q = atomicAdd(&s_cnt, 1); if (q < COLLECT_CAP) s_buf[q] = 8 * i + 2 * w + 1; }
        }
    }
    __syncthreads();
    int cnt = s_cnt;
    if (cnt > COLLECT_CAP) cnt = COLLECT_CAP;
    if (threadIdx.x == 0) s_base = atomicAdd(&g_cand_cnt, (unsigned int)cnt);
    __syncthreads();
    unsigned int base = s_base;
    for (int j = threadIdx.x; j < cnt; j += blockDim.x) {
        unsigned int p = base + j;
        if (p < CAND_CAP) g_cand_idx[p] = s_buf[j];
    }
}

// ---------------------------------------------------------------------------
// resolve: recompute exact 32-bit keys for candidates, histogram low 20 bits.
// ---------------------------------------------------------------------------
__global__ void __launch_bounds__(256) resolve_k(
        const float* __restrict__ logits,
        const float* __restrict__ u1,
        const int* __restrict__ training) {
    const int tr = *training;
    unsigned int m = g_cand_cnt;
    if (m > CAND_CAP) m = CAND_CAP;
    const unsigned int stride = gridDim.x * blockDim.x;
    for (unsigned int i = blockIdx.x * blockDim.x + threadIdx.x; i < m; i += stride) {
        int idx = g_cand_idx[i];
        float l = __ldg(&logits[idx]);
        float u = __ldg(&u1[idx]);
        unsigned int key = f2key(tr ? (l + gum(u)) : l);
        g_cand_key[i] = key;
        atomicAdd(&g_hist2[key & 0xFFFFFu], 1u);
    }
}

// chunk sums of hist2 (1024 chunks of 1024 bins)
__global__ void chunksum2_k() {
    __shared__ unsigned int sh[256];
    int b = blockIdx.x;
    unsigned int s = 0;
    for (int j = threadIdx.x; j < 1024; j += 256) s += g_hist2[b * 1024 + j];
    sh[threadIdx.x] = s;
    __syncthreads();
    for (int off = 128; off > 0; off >>= 1) {
        if (threadIdx.x < off) sh[threadIdx.x] += sh[threadIdx.x + off];
        __syncthreads();
    }
    if (threadIdx.x == 0) g_csum2[b] = sh[0];
}

// select level 2: exact threshold key T and r = #(==T) to include
__global__ void select2_k() {
    __shared__ unsigned int sh[1024];
    __shared__ unsigned int s_chunk, s_k2;
    int t = threadIdx.x;
    const unsigned int k1 = g_k1;
    unsigned int s = g_csum2[1023 - t];
    unsigned int incl = block_incl_scan(s, sh);
    unsigned int excl = incl - s;
    if (excl < k1 && k1 <= incl) { s_chunk = 1023 - t; s_k2 = k1 - excl; }
    __syncthreads();
    const unsigned int a = s_chunk;
    const unsigned int k2 = s_k2;
    unsigned int bin = a * 1024 + 1023 - t;
    unsigned int cb = g_hist2[bin];
    __syncthreads();
    unsigned int incl2 = block_incl_scan(cb, sh);
    unsigned int excl2 = incl2 - cb;
    if (excl2 < k2 && k2 <= incl2) {
        g_T = (g_prefix12 << 20) | bin;
        g_r = k2 - excl2;
    }
}

// ---------------------------------------------------------------------------
// ties among candidates: exact key == T; then cutoff = r-th smallest index
// ---------------------------------------------------------------------------
__global__ void tie_collect_k() {
    const unsigned int T = g_T;
    unsigned int m = g_cand_cnt;
    if (m > CAND_CAP) m = CAND_CAP;
    const unsigned int stride = gridDim.x * blockDim.x;
    for (unsigned int i = blockIdx.x * blockDim.x + threadIdx.x; i < m; i += stride) {
        if (g_cand_key[i] == T) {
            unsigned int p = atomicAdd(&g_tie_cnt, 1u);
            if (p < TIE_CAP) g_tie_idx[p] = g_cand_idx[i];
        }
    }
}

__global__ void cutoff_k(int n) {
    __shared__ int s_cnt;
    unsigned int m = g_tie_cnt;
    if (m > TIE_CAP) m = TIE_CAP;
    const unsigned int r = g_r;
    if (r == 0 || m == 0) { if (threadIdx.x == 0) g_cutoff = -1; return; }
    int lo = 0, hi = n - 1;
    while (lo < hi) {
        int mid = lo + (hi - lo) / 2;
        if (threadIdx.x == 0) s_cnt = 0;
        __syncthreads();
        int c = 0;
        for (unsigned int j = threadIdx.x; j < m; j += blockDim.x)
            if (g_tie_idx[j] <= mid) c++;
        if (c) atomicAdd(&s_cnt, c);
        __syncthreads();
        if (s_cnt >= (int)r) hi = mid; else lo = mid + 1;
        __syncthreads();
    }
    if (threadIdx.x == 0) g_cutoff = lo;
}

// ---------------------------------------------------------------------------
// final: stream key16 + u2 -> out. top12 > pfx: mask 1; else mask 0
// (ambiguous elements provisional 0; fixup2 rewrites the included ones).
// ---------------------------------------------------------------------------
__device__ __forceinline__ float out_elem16(unsigned int key16, float v0, float v1,
                                            unsigned int pfx4, int tr) {
    float m = ((key16 & 0xFFF0u) > pfx4) ? 1.0f : 0.0f;
    if (!tr) return m;
    return (m + gum(v1) > gum(v0)) ? 1.0f : 0.0f;
}

__global__ void __launch_bounds__(256) final_k(
        const float* __restrict__ u2,
        const int* __restrict__ training,
        float* __restrict__ out, int n4) {
    const unsigned int pfx4 = g_prefix12 << 4;
    const int tr = *training;
    const int stride = gridDim.x * blockDim.x;
    int i = blockIdx.x * blockDim.x + threadIdx.x;
    for (; i + stride < n4; i += 2 * stride) {
        uint2 p0 = ((const uint2*)g_key16)[i];
        float4 a0 = __ldcs((const float4*)u2 + 2 * i);
        float4 b0 = __ldcs((const float4*)u2 + 2 * i + 1);
        uint2 p1 = ((const uint2*)g_key16)[i + stride];
        float4 a1 = __ldcs((const float4*)u2 + 2 * (i + stride));
        float4 b1 = __ldcs((const float4*)u2 + 2 * (i + stride) + 1);
        float4 o0, o1;
        o0.x = out_elem16(p0.x & 0xFFFFu, a0.x, a0.y, pfx4, tr);
        o0.y = out_elem16(p0.x >> 16,     a0.z, a0.w, pfx4, tr);
        o0.z = out_elem16(p0.y & 0xFFFFu, b0.x, b0.y, pfx4, tr);
        o0.w = out_elem16(p0.y >> 16,     b0.z, b0.w, pfx4, tr);
        o1.x = out_elem16(p1.x & 0xFFFFu, a1.x, a1.y, pfx4, tr);
        o1.y = out_elem16(p1.x >> 16,     a1.z, a1.w, pfx4, tr);
        o1.z = out_elem16(p1.y & 0xFFFFu, b1.x, b1.y, pfx4, tr);
        o1.w = out_elem16(p1.y >> 16,     b1.z, b1.w, pfx4, tr);
        __stcs((float4*)out + i, o0);
        __stcs((float4*)out + i + stride, o1);
    }
    for (; i < n4; i += stride) {
        uint2 p = ((const uint2*)g_key16)[i];
        float4 a = __ldcs((const float4*)u2 + 2 * i);
        float4 b = __ldcs((const float4*)u2 + 2 * i + 1);
        float4 o;
        o.x = out_elem16(p.x & 0xFFFFu, a.x, a.y, pfx4, tr);
        o.y = out_elem16(p.x >> 16,     a.z, a.w, pfx4, tr);
        o.z = out_elem16(p.y & 0xFFFFu, b.x, b.y, pfx4, tr);
        o.w = out_elem16(p.y >> 16,     b.z, b.w, pfx4, tr);
        __stcs((float4*)out + i, o);
    }
}

// ---------------------------------------------------------------------------
// fixup2: stream candidate list; included = key > T or (key==T && idx<=cutoff).
// Rewrite out[idx] with the mask=1 result.
// ---------------------------------------------------------------------------
__global__ void __launch_bounds__(256) fixup2_k(
        const float* __restrict__ u2,
        const int* __restrict__ training,
        float* __restrict__ out) {
    const unsigned int T = g_T;
    const int cutoff = g_cutoff;
    const int tr = *training;
    unsigned int m = g_cand_cnt;
    if (m > CAND_CAP) m = CAND_CAP;
    const unsigned int stride = gridDim.x * blockDim.x;
    for (unsigned int i = blockIdx.x * blockDim.x + threadIdx.x; i < m; i += stride) {
        unsigned int key = g_cand_key[i];
        if (key > T || (key == T && g_cand_idx[i] <= cutoff)) {
            int idx = g_cand_idx[i];
            float v = 1.0f;
            if (tr) {
                float2 uu = __ldg((const float2*)u2 + idx);
                v = (1.0f + gum(uu.y) > gum(uu.x)) ? 1.0f : 0.0f;
            }
            out[idx] = v;
        }
    }
}

// ---------------------------------------------------------------------------
extern "C" void kernel_launch(void* const* d_in, const int* in_sizes, int n_in,
                              void* d_out, int out_size) {
    const float* mask_logits = (const float*)d_in[0];
    const float* u1          = (const float*)d_in[1];
    const float* u2          = (const float*)d_in[2];
    const int*   kp          = (const int*)d_in[3];
    const int*   training    = (const int*)d_in[4];
    float* out = (float*)d_out;

    const int n  = in_sizes[0];
    const int n4 = n / 4;
    const int n8 = n / 8;

    reset_k<<<1024, 256>>>();
    score16_k<<<2048, 256>>>(mask_logits, u1, training, n4);
    select1_k<<<1, 1024>>>(kp);
    collect_k<<<2048, 256>>>(n8);
    resolve_k<<<1024, 256>>>(mask_logits, u1, training);
    chunksum2_k<<<1024, 256>>>();
    select2_k<<<1, 1024>>>();
    tie_collect_k<<<256, 256>>>();
    cutoff_k<<<1, 1024>>>(n);
    final_k<<<4096, 256>>>(u2, training, out, n4);
    fixup2_k<<<1024, 256>>>(u2, training, out);
}

// round 10
// speedup vs baseline: 1.0795x; 1.0083x over previous
#include <cuda_runtime.h>
#include <cuda_bf16.h>
#include <stdint.h>

// ============================================================================
// GumbelTopK R10: R3 pipeline + code-emitting hist2.
//  A:        score -> keys32 (64MB) + 12-bit smem hist          [192MB]
//  select1:  12-bit bin holding rank k
//  hist2col: read keys (once, __ldcs); hist low-20 of in-bin;
//            emit 2-bit code/elem (4MB); append in-bin {key,idx} [68MB]
//  select2:  exact threshold T + rank r (over in-bin histogram)
//  ties:     cand key==T -> cutoff index
//  final:    codes (4MB) + u2 (128MB) -> out (64MB); in-bin = provisional 0
//  fixup2:   rewrite included candidates with mask=1            [~15MB rnd]
// ============================================================================

#define N_MAX    (1u << 24)      // 4096*4096
#define H1_BINS  4096            // top 12 bits
#define H2_BINS  (1u << 20)      // low 20 bits
#define CAND_CAP (1u << 22)
#define TIE_CAP  (1u << 20)
#define CCAP     4096            // per-block candidate staging
#define EPSF     1e-8f

__device__ unsigned int g_keys[N_MAX];
__device__ unsigned int g_code[N_MAX / 16];   // 2 bits per element
__device__ unsigned int g_cand_key[CAND_CAP];
__device__ int          g_cand_idx[CAND_CAP];
__device__ int          g_tie_idx[TIE_CAP];
__device__ unsigned int g_hist1[H1_BINS];
__device__ unsigned int g_hist2[H2_BINS];
__device__ unsigned int g_csum2[1024];
__device__ unsigned int g_cand_cnt;
__device__ unsigned int g_tie_cnt;
__device__ unsigned int g_prefix12;
__device__ unsigned int g_k1;
__device__ unsigned int g_T;
__device__ unsigned int g_r;
__device__ int          g_cutoff;

__device__ __forceinline__ float gum(float u) {
    return -logf(-logf(u + EPSF) + EPSF);
}

__device__ __forceinline__ unsigned int f2key(float f) {
    unsigned int b = __float_as_uint(f);
    return (b & 0x80000000u) ? ~b : (b | 0x80000000u);
}

// ---------------------------------------------------------------------------
__global__ void reset_k() {
    int stride = gridDim.x * blockDim.x;
    for (unsigned int i = blockIdx.x * blockDim.x + threadIdx.x; i < H2_BINS; i += stride)
        g_hist2[i] = 0;
    unsigned int t = blockIdx.x * blockDim.x + threadIdx.x;
    if (t < H1_BINS) g_hist1[t] = 0;
    if (t == 0) { g_cand_cnt = 0; g_tie_cnt = 0; }
}

// ---------------------------------------------------------------------------
// pass A: score + key store + 12-bit histogram (2-way replicated smem) — R3.
// ---------------------------------------------------------------------------
__global__ void __launch_bounds__(256) score_hist_k(
        const float* __restrict__ logits,
        const float* __restrict__ u1,
        const int* __restrict__ training, int n4) {
    __shared__ unsigned int sh[2 * H1_BINS];     // 32 KB
    for (int i = threadIdx.x; i < 2 * H1_BINS; i += blockDim.x) sh[i] = 0;
    __syncthreads();
    unsigned int* mysh = sh + ((threadIdx.x >> 5) & 1) * H1_BINS;
    const int tr = *training;
    const int stride = gridDim.x * blockDim.x;
    int i = blockIdx.x * blockDim.x + threadIdx.x;
    for (; i + stride < n4; i += 2 * stride) {
        float4 l0 = __ldcs((const float4*)logits + i);
        float4 u0 = __ldcs((const float4*)u1 + i);
        float4 l1 = __ldcs((const float4*)logits + i + stride);
        float4 u1v = __ldcs((const float4*)u1 + i + stride);
        uint4 k0, k1;
        k0.x = f2key(tr ? (l0.x + gum(u0.x)) : l0.x);
        k0.y = f2key(tr ? (l0.y + gum(u0.y)) : l0.y);
        k0.z = f2key(tr ? (l0.z + gum(u0.z)) : l0.z);
        k0.w = f2key(tr ? (l0.w + gum(u0.w)) : l0.w);
        k1.x = f2key(tr ? (l1.x + gum(u1v.x)) : l1.x);
        k1.y = f2key(tr ? (l1.y + gum(u1v.y)) : l1.y);
        k1.z = f2key(tr ? (l1.z + gum(u1v.z)) : l1.z);
        k1.w = f2key(tr ? (l1.w + gum(u1v.w)) : l1.w);
        ((uint4*)g_keys)[i] = k0;
        ((uint4*)g_keys)[i + stride] = k1;
        atomicAdd(&mysh[k0.x >> 20], 1u);
        atomicAdd(&mysh[k0.y >> 20], 1u);
        atomicAdd(&mysh[k0.z >> 20], 1u);
        atomicAdd(&mysh[k0.w >> 20], 1u);
        atomicAdd(&mysh[k1.x >> 20], 1u);
        atomicAdd(&mysh[k1.y >> 20], 1u);
        atomicAdd(&mysh[k1.z >> 20], 1u);
        atomicAdd(&mysh[k1.w >> 20], 1u);
    }
    for (; i < n4; i += stride) {
        float4 l = __ldcs((const float4*)logits + i);
        float4 u = __ldcs((const float4*)u1 + i);
        uint4 kk;
        kk.x = f2key(tr ? (l.x + gum(u.x)) : l.x);
        kk.y = f2key(tr ? (l.y + gum(u.y)) : l.y);
        kk.z = f2key(tr ? (l.z + gum(u.z)) : l.z);
        kk.w = f2key(tr ? (l.w + gum(u.w)) : l.w);
        ((uint4*)g_keys)[i] = kk;
        atomicAdd(&mysh[kk.x >> 20], 1u);
        atomicAdd(&mysh[kk.y >> 20], 1u);
        atomicAdd(&mysh[kk.z >> 20], 1u);
        atomicAdd(&mysh[kk.w >> 20], 1u);
    }
    __syncthreads();
    for (int b = threadIdx.x; b < H1_BINS; b += blockDim.x) {
        unsigned int c = sh[b] + sh[b + H1_BINS];
        if (c) atomicAdd(&g_hist1[b], c);
    }
}

// ---------------------------------------------------------------------------
__device__ __forceinline__ unsigned int block_incl_scan(unsigned int v, unsigned int* sh) {
    int t = threadIdx.x;
    sh[t] = v;
    __syncthreads();
    for (int off = 1; off < blockDim.x; off <<= 1) {
        unsigned int add = (t >= off) ? sh[t - off] : 0u;
        __syncthreads();
        sh[t] += add;
        __syncthreads();
    }
    return sh[t];
}

// select level 1: 12-bit bin holding rank-k (descending)
__global__ void select1_k(const int* __restrict__ kp) {
    __shared__ unsigned int sh[1024];
    const unsigned int k = (unsigned int)(*kp);
    int t = threadIdx.x;
    unsigned int c[4], s = 0;
#pragma unroll
    for (int j = 0; j < 4; j++) { c[j] = g_hist1[4095 - (4 * t + j)]; s += c[j]; }
    unsigned int incl = block_incl_scan(s, sh);
    unsigned int excl = incl - s;
    if (excl < k && k <= incl) {
        unsigned int cum = excl;
#pragma unroll
        for (int j = 0; j < 4; j++) {
            if (cum + c[j] >= k) { g_prefix12 = 4095 - (4 * t + j); g_k1 = k - cum; break; }
            cum += c[j];
        }
    }
}

// ---------------------------------------------------------------------------
// hist2collect: the single full read of keys. Per 16 elements produce one
// 2-bit-per-elem code word; in-bin elements feed the 20-bit histogram and a
// block-aggregated candidate list.
// ---------------------------------------------------------------------------
__global__ void __launch_bounds__(256) hist2collect_k(int n16) {
    __shared__ uint2 s_buf[CCAP];      // 32 KB
    __shared__ int s_cnt;
    __shared__ unsigned int s_base;
    if (threadIdx.x == 0) s_cnt = 0;
    __syncthreads();
    const unsigned int pfx = g_prefix12;
    const int stride = gridDim.x * blockDim.x;
    for (int w = blockIdx.x * blockDim.x + threadIdx.x; w < n16; w += stride) {
        unsigned int word = 0;
#pragma unroll
        for (int q = 0; q < 4; q++) {
            uint4 kk = __ldcs((const uint4*)g_keys + 4 * w + q);
#pragma unroll
            for (int j = 0; j < 4; j++) {
                unsigned int key = (j == 0) ? kk.x : (j == 1) ? kk.y : (j == 2) ? kk.z : kk.w;
                unsigned int top = key >> 20;
                unsigned int code = (top > pfx) ? 1u : ((top == pfx) ? 2u : 0u);
                word |= code << (2 * (4 * q + j));
                if (code == 2u) {
                    atomicAdd(&g_hist2[key & 0xFFFFFu], 1u);
                    int qq = atomicAdd(&s_cnt, 1);
                    if (qq < CCAP) s_buf[qq] = make_uint2(key, (unsigned int)(16 * w + 4 * q + j));
                }
            }
        }
        g_code[w] = word;
    }
    __syncthreads();
    int cnt = s_cnt;
    if (cnt > CCAP) cnt = CCAP;
    if (threadIdx.x == 0) s_base = atomicAdd(&g_cand_cnt, (unsigned int)cnt);
    __syncthreads();
    unsigned int base = s_base;
    for (int j = threadIdx.x; j < cnt; j += blockDim.x) {
        unsigned int p = base + j;
        if (p < CAND_CAP) {
            g_cand_key[p] = s_buf[j].x;
            g_cand_idx[p] = (int)s_buf[j].y;
        }
    }
}

// chunk sums of hist2 (1024 chunks of 1024 bins)
__global__ void chunksum2_k() {
    __shared__ unsigned int sh[256];
    int b = blockIdx.x;
    unsigned int s = 0;
    for (int j = threadIdx.x; j < 1024; j += 256) s += g_hist2[b * 1024 + j];
    sh[threadIdx.x] = s;
    __syncthreads();
    for (int off = 128; off > 0; off >>= 1) {
        if (threadIdx.x < off) sh[threadIdx.x] += sh[threadIdx.x + off];
        __syncthreads();
    }
    if (threadIdx.x == 0) g_csum2[b] = sh[0];
}

// select level 2: exact threshold key T and r = #(==T) to include
__global__ void select2_k() {
    __shared__ unsigned int sh[1024];
    __shared__ unsigned int s_chunk, s_k2;
    int t = threadIdx.x;
    const unsigned int k1 = g_k1;
    unsigned int s = g_csum2[1023 - t];
    unsigned int incl = block_incl_scan(s, sh);
    unsigned int excl = incl - s;
    if (excl < k1 && k1 <= incl) { s_chunk = 1023 - t; s_k2 = k1 - excl; }
    __syncthreads();
    const unsigned int a = s_chunk;
    const unsigned int k2 = s_k2;
    unsigned int bin = a * 1024 + 1023 - t;
    unsigned int cb = g_hist2[bin];
    __syncthreads();
    unsigned int incl2 = block_incl_scan(cb, sh);
    unsigned int excl2 = incl2 - cb;
    if (excl2 < k2 && k2 <= incl2) {
        g_T = (g_prefix12 << 20) | bin;
        g_r = k2 - excl2;
    }
}

// ---------------------------------------------------------------------------
// ties among candidates: exact key == T; then cutoff = r-th smallest index
// ---------------------------------------------------------------------------
__global__ void tie_collect_k() {
    const unsigned int T = g_T;
    unsigned int m = g_cand_cnt;
    if (m > CAND_CAP) m = CAND_CAP;
    const unsigned int stride = gridDim.x * blockDim.x;
    for (unsigned int i = blockIdx.x * blockDim.x + threadIdx.x; i < m; i += stride) {
        if (g_cand_key[i] == T) {
            unsigned int p = atomicAdd(&g_tie_cnt, 1u);
            if (p < TIE_CAP) g_tie_idx[p] = g_cand_idx[i];
        }
    }
}

__global__ void cutoff_k(int n) {
    __shared__ int s_cnt;
    unsigned int m = g_tie_cnt;
    if (m > TIE_CAP) m = TIE_CAP;
    const unsigned int r = g_r;
    if (r == 0 || m == 0) { if (threadIdx.x == 0) g_cutoff = -1; return; }
    int lo = 0, hi = n - 1;
    while (lo < hi) {
        int mid = lo + (hi - lo) / 2;
        if (threadIdx.x == 0) s_cnt = 0;
        __syncthreads();
        int c = 0;
        for (unsigned int j = threadIdx.x; j < m; j += blockDim.x)
            if (g_tie_idx[j] <= mid) c++;
        if (c) atomicAdd(&s_cnt, c);
        __syncthreads();
        if (s_cnt >= (int)r) hi = mid; else lo = mid + 1;
        __syncthreads();
    }
    if (threadIdx.x == 0) g_cutoff = lo;
}

// ---------------------------------------------------------------------------
// final: codes (2 bits/elem, L2-resident) + u2 stream -> out.
// code 1 -> mask 1; code 0 or 2 -> mask 0 (in-bin fixed by fixup2).
// ---------------------------------------------------------------------------
__device__ __forceinline__ float out_code(unsigned int code, float v0, float v1, int tr) {
    float m = (code == 1u) ? 1.0f : 0.0f;
    if (!tr) return m;
    return (m + gum(v1) > gum(v0)) ? 1.0f : 0.0f;
}

__global__ void __launch_bounds__(256) final_k(
        const float* __restrict__ u2,
        const int* __restrict__ training,
        float* __restrict__ out, int n4) {
    const int tr = *training;
    const int stride = gridDim.x * blockDim.x;
    int i = blockIdx.x * blockDim.x + threadIdx.x;
    for (; i + stride < n4; i += 2 * stride) {
        unsigned int w0 = __ldg(&g_code[i >> 2]);
        unsigned int w1 = __ldg(&g_code[(i + stride) >> 2]);
        unsigned int c0 = (w0 >> ((i & 3) * 8)) & 0xFFu;
        unsigned int c1 = (w1 >> (((i + stride) & 3) * 8)) & 0xFFu;
        float4 a0 = __ldcs((const float4*)u2 + 2 * i);
        float4 b0 = __ldcs((const float4*)u2 + 2 * i + 1);
        float4 a1 = __ldcs((const float4*)u2 + 2 * (i + stride));
        float4 b1 = __ldcs((const float4*)u2 + 2 * (i + stride) + 1);
        float4 o0, o1;
        o0.x = out_code((c0 >> 0) & 3u, a0.x, a0.y, tr);
        o0.y = out_code((c0 >> 2) & 3u, a0.z, a0.w, tr);
        o0.z = out_code((c0 >> 4) & 3u, b0.x, b0.y, tr);
        o0.w = out_code((c0 >> 6) & 3u, b0.z, b0.w, tr);
        o1.x = out_code((c1 >> 0) & 3u, a1.x, a1.y, tr);
        o1.y = out_code((c1 >> 2) & 3u, a1.z, a1.w, tr);
        o1.z = out_code((c1 >> 4) & 3u, b1.x, b1.y, tr);
        o1.w = out_code((c1 >> 6) & 3u, b1.z, b1.w, tr);
        __stcs((float4*)out + i, o0);
        __stcs((float4*)out + i + stride, o1);
    }
    for (; i < n4; i += stride) {
        unsigned int w = __ldg(&g_code[i >> 2]);
        unsigned int c = (w >> ((i & 3) * 8)) & 0xFFu;
        float4 a = __ldcs((const float4*)u2 + 2 * i);
        float4 b = __ldcs((const float4*)u2 + 2 * i + 1);
        float4 o;
        o.x = out_code((c >> 0) & 3u, a.x, a.y, tr);
        o.y = out_code((c >> 2) & 3u, a.z, a.w, tr);
        o.z = out_code((c >> 4) & 3u, b.x, b.y, tr);
        o.w = out_code((c >> 6) & 3u, b.z, b.w, tr);
        __stcs((float4*)out + i, o);
    }
}

// ---------------------------------------------------------------------------
// fixup2: included candidates (key > T, or == T with idx <= cutoff) get mask=1.
// ---------------------------------------------------------------------------
__global__ void __launch_bounds__(256) fixup2_k(
        const float* __restrict__ u2,
        const int* __restrict__ training,
        float* __restrict__ out) {
    const unsigned int T = g_T;
    const int cutoff = g_cutoff;
    const int tr = *training;
    unsigned int m = g_cand_cnt;
    if (m > CAND_CAP) m = CAND_CAP;
    const unsigned int stride = gridDim.x * blockDim.x;
    for (unsigned int i = blockIdx.x * blockDim.x + threadIdx.x; i < m; i += stride) {
        unsigned int key = g_cand_key[i];
        if (key > T || (key == T && g_cand_idx[i] <= cutoff)) {
            int idx = g_cand_idx[i];
            float v = 1.0f;
            if (tr) {
                float2 uu = __ldg((const float2*)u2 + idx);
                v = (1.0f + gum(uu.y) > gum(uu.x)) ? 1.0f : 0.0f;
            }
            out[idx] = v;
        }
    }
}

// ---------------------------------------------------------------------------
extern "C" void kernel_launch(void* const* d_in, const int* in_sizes, int n_in,
                              void* d_out, int out_size) {
    const float* mask_logits = (const float*)d_in[0];
    const float* u1          = (const float*)d_in[1];
    const float* u2          = (const float*)d_in[2];
    const int*   kp          = (const int*)d_in[3];
    const int*   training    = (const int*)d_in[4];
    float* out = (float*)d_out;

    const int n   = in_sizes[0];
    const int n4  = n / 4;
    const int n16 = n / 16;

    reset_k<<<1024, 256>>>();
    score_hist_k<<<2048, 256>>>(mask_logits, u1, training, n4);
    select1_k<<<1, 1024>>>(kp);
    hist2collect_k<<<2048, 256>>>(n16);
    chunksum2_k<<<1024, 256>>>();
    select2_k<<<1, 1024>>>();
    tie_collect_k<<<256, 256>>>();
    cutoff_k<<<1, 1024>>>(n);
    final_k<<<4096, 256>>>(u2, training, out, n4);
    fixup2_k<<<1024, 256>>>(u2, training, out);
}

// round 12
// speedup vs baseline: 1.2236x; 1.1334x over previous
#include <cuda_runtime.h>
#include <cuda_bf16.h>
#include <stdint.h>

// ============================================================================
// GumbelTopK R12 (= R11 resubmitted after infra flake): R3 select machinery
// + ballot flags + logf-free final.
//  A:      score -> keys32 (64MB W) + 12-bit smem hist            [192MB]
//  select1: 12-bit bin holding rank k
//  flags:  keys (__ldcs, once) -> above/inbin bitmasks via ballot [68MB]
//  cand:   inbin bitmask (2MB) -> gather keys -> hist2 + cand list [small]
//  select2/ties/cutoff: exact threshold T, rank r, index cutoff
//  final:  above bits (2MB) + u2 (128MB) -> out (64MB),
//          m=0: u1>u0 (0 logf); m=1: a1 < e*a0 (2 logf)           [194MB]
//  fixup2: included candidates rewritten with exact gumbel
// ============================================================================

#define N_MAX    (1u << 24)      // 4096*4096
#define H1_BINS  4096
#define H2_BINS  (1u << 20)
#define CAND_CAP (1u << 22)
#define TIE_CAP  (1u << 20)
#define CCAP     4096
#define EPSF     1e-8f
#define EULER_F  2.7182818284590452f

__device__ unsigned int g_keys[N_MAX];
__device__ unsigned int g_above[N_MAX / 32];
__device__ unsigned int g_inbin[N_MAX / 32];
__device__ unsigned int g_cand_key[CAND_CAP];
__device__ int          g_cand_idx[CAND_CAP];
__device__ int          g_tie_idx[TIE_CAP];
__device__ unsigned int g_hist1[H1_BINS];
__device__ unsigned int g_hist2[H2_BINS];
__device__ unsigned int g_csum2[1024];
__device__ unsigned int g_cand_cnt;
__device__ unsigned int g_tie_cnt;
__device__ unsigned int g_prefix12;
__device__ unsigned int g_k1;
__device__ unsigned int g_T;
__device__ unsigned int g_r;
__device__ int          g_cutoff;

__device__ __forceinline__ float gum(float u) {
    return -logf(-logf(u + EPSF) + EPSF);
}

__device__ __forceinline__ unsigned int f2key(float f) {
    unsigned int b = __float_as_uint(f);
    return (b & 0x80000000u) ? ~b : (b | 0x80000000u);
}

// ---------------------------------------------------------------------------
__global__ void reset_k() {
    int stride = gridDim.x * blockDim.x;
    for (unsigned int i = blockIdx.x * blockDim.x + threadIdx.x; i < H2_BINS; i += stride)
        g_hist2[i] = 0;
    unsigned int t = blockIdx.x * blockDim.x + threadIdx.x;
    if (t < H1_BINS) g_hist1[t] = 0;
    if (t == 0) { g_cand_cnt = 0; g_tie_cnt = 0; }
}

// ---------------------------------------------------------------------------
// pass A: score + key store + 12-bit histogram (2-way replicated smem) — R3.
// ---------------------------------------------------------------------------
__global__ void __launch_bounds__(256) score_hist_k(
        const float* __restrict__ logits,
        const float* __restrict__ u1,
        const int* __restrict__ training, int n4) {
    __shared__ unsigned int sh[2 * H1_BINS];     // 32 KB
    for (int i = threadIdx.x; i < 2 * H1_BINS; i += blockDim.x) sh[i] = 0;
    __syncthreads();
    unsigned int* mysh = sh + ((threadIdx.x >> 5) & 1) * H1_BINS;
    const int tr = *training;
    const int stride = gridDim.x * blockDim.x;
    int i = blockIdx.x * blockDim.x + threadIdx.x;
    for (; i + stride < n4; i += 2 * stride) {
        float4 l0 = __ldcs((const float4*)logits + i);
        float4 u0 = __ldcs((const float4*)u1 + i);
        float4 l1 = __ldcs((const float4*)logits + i + stride);
        float4 u1v = __ldcs((const float4*)u1 + i + stride);
        uint4 k0, k1;
        k0.x = f2key(tr ? (l0.x + gum(u0.x)) : l0.x);
        k0.y = f2key(tr ? (l0.y + gum(u0.y)) : l0.y);
        k0.z = f2key(tr ? (l0.z + gum(u0.z)) : l0.z);
        k0.w = f2key(tr ? (l0.w + gum(u0.w)) : l0.w);
        k1.x = f2key(tr ? (l1.x + gum(u1v.x)) : l1.x);
        k1.y = f2key(tr ? (l1.y + gum(u1v.y)) : l1.y);
        k1.z = f2key(tr ? (l1.z + gum(u1v.z)) : l1.z);
        k1.w = f2key(tr ? (l1.w + gum(u1v.w)) : l1.w);
        ((uint4*)g_keys)[i] = k0;
        ((uint4*)g_keys)[i + stride] = k1;
        atomicAdd(&mysh[k0.x >> 20], 1u);
        atomicAdd(&mysh[k0.y >> 20], 1u);
        atomicAdd(&mysh[k0.z >> 20], 1u);
        atomicAdd(&mysh[k0.w >> 20], 1u);
        atomicAdd(&mysh[k1.x >> 20], 1u);
        atomicAdd(&mysh[k1.y >> 20], 1u);
        atomicAdd(&mysh[k1.z >> 20], 1u);
        atomicAdd(&mysh[k1.w >> 20], 1u);
    }
    for (; i < n4; i += stride) {
        float4 l = __ldcs((const float4*)logits + i);
        float4 u = __ldcs((const float4*)u1 + i);
        uint4 kk;
        kk.x = f2key(tr ? (l.x + gum(u.x)) : l.x);
        kk.y = f2key(tr ? (l.y + gum(u.y)) : l.y);
        kk.z = f2key(tr ? (l.z + gum(u.z)) : l.z);
        kk.w = f2key(tr ? (l.w + gum(u.w)) : l.w);
        ((uint4*)g_keys)[i] = kk;
        atomicAdd(&mysh[kk.x >> 20], 1u);
        atomicAdd(&mysh[kk.y >> 20], 1u);
        atomicAdd(&mysh[kk.z >> 20], 1u);
        atomicAdd(&mysh[kk.w >> 20], 1u);
    }
    __syncthreads();
    for (int b = threadIdx.x; b < H1_BINS; b += blockDim.x) {
        unsigned int c = sh[b] + sh[b + H1_BINS];
        if (c) atomicAdd(&g_hist1[b], c);
    }
}

// ---------------------------------------------------------------------------
__device__ __forceinline__ unsigned int block_incl_scan(unsigned int v, unsigned int* sh) {
    int t = threadIdx.x;
    sh[t] = v;
    __syncthreads();
    for (int off = 1; off < blockDim.x; off <<= 1) {
        unsigned int add = (t >= off) ? sh[t - off] : 0u;
        __syncthreads();
        sh[t] += add;
        __syncthreads();
    }
    return sh[t];
}

// select level 1: 12-bit bin holding rank-k (descending)
__global__ void select1_k(const int* __restrict__ kp) {
    __shared__ unsigned int sh[1024];
    const unsigned int k = (unsigned int)(*kp);
    int t = threadIdx.x;
    unsigned int c[4], s = 0;
#pragma unroll
    for (int j = 0; j < 4; j++) { c[j] = g_hist1[4095 - (4 * t + j)]; s += c[j]; }
    unsigned int incl = block_incl_scan(s, sh);
    unsigned int excl = incl - s;
    if (excl < k && k <= incl) {
        unsigned int cum = excl;
#pragma unroll
        for (int j = 0; j < 4; j++) {
            if (cum + c[j] >= k) { g_prefix12 = 4095 - (4 * t + j); g_k1 = k - cum; break; }
            cum += c[j];
        }
    }
}

// ---------------------------------------------------------------------------
// flags: single full read of keys. Ballot-emit per-element above/inbin bits.
// Element e = 4*i + j -> word 4*(i>>5)+j, bit (i&31). All lanes of a warp
// share i>>5 (grid stride is a multiple of 32; n4 divides evenly).
// ---------------------------------------------------------------------------
__global__ void __launch_bounds__(256) flags_k(int n4) {
    const unsigned int pfx = g_prefix12;
    const int stride = gridDim.x * blockDim.x;
    const int lane = threadIdx.x & 31;
    for (int i = blockIdx.x * blockDim.x + threadIdx.x; i < n4; i += stride) {
        uint4 kk = __ldcs((const uint4*)g_keys + i);
        int B = i >> 5;
#pragma unroll
        for (int j = 0; j < 4; j++) {
            unsigned int key = (j == 0) ? kk.x : (j == 1) ? kk.y : (j == 2) ? kk.z : kk.w;
            unsigned int top = key >> 20;
            unsigned int ab = __ballot_sync(0xFFFFFFFFu, top > pfx);
            unsigned int ib = __ballot_sync(0xFFFFFFFFu, top == pfx);
            if (lane == 0) {
                g_above[4 * B + j] = ab;
                g_inbin[4 * B + j] = ib;
            }
        }
    }
}

// ---------------------------------------------------------------------------
// cand: read inbin bitmask (2MB); for set bits gather exact key, feed the
// 20-bit histogram and the block-staged candidate list.
// word W: B=W>>2, j=W&3; bit lane -> element 128*B + 4*lane + j.
// ---------------------------------------------------------------------------
__global__ void __launch_bounds__(256) cand_k(int n32) {
    __shared__ uint2 s_buf[CCAP];    // 32 KB
    __shared__ int s_cnt;
    __shared__ unsigned int s_base;
    if (threadIdx.x == 0) s_cnt = 0;
    __syncthreads();
    const int stride = gridDim.x * blockDim.x;
    for (int w = blockIdx.x * blockDim.x + threadIdx.x; w < n32; w += stride) {
        unsigned int word = g_inbin[w];
        int B = w >> 2, j = w & 3;
        while (word) {
            int bit = __ffs(word) - 1;
            word &= word - 1;
            int e = 128 * B + 4 * bit + j;
            unsigned int key = __ldg(&g_keys[e]);
            atomicAdd(&g_hist2[key & 0xFFFFFu], 1u);
            int q = atomicAdd(&s_cnt, 1);
            if (q < CCAP) s_buf[q] = make_uint2(key, (unsigned int)e);
        }
    }
    __syncthreads();
    int cnt = s_cnt;
    if (cnt > CCAP) cnt = CCAP;
    if (threadIdx.x == 0) s_base = atomicAdd(&g_cand_cnt, (unsigned int)cnt);
    __syncthreads();
    unsigned int base = s_base;
    for (int t = threadIdx.x; t < cnt; t += blockDim.x) {
        unsigned int p = base + t;
        if (p < CAND_CAP) {
            g_cand_key[p] = s_buf[t].x;
            g_cand_idx[p] = (int)s_buf[t].y;
        }
    }
}

// chunk sums of hist2 (1024 chunks of 1024 bins)
__global__ void chunksum2_k() {
    __shared__ unsigned int sh[256];
    int b = blockIdx.x;
    unsigned int s = 0;
    for (int j = threadIdx.x; j < 1024; j += 256) s += g_hist2[b * 1024 + j];
    sh[threadIdx.x] = s;
    __syncthreads();
    for (int off = 128; off > 0; off >>= 1) {
        if (threadIdx.x < off) sh[threadIdx.x] += sh[threadIdx.x + off];
        __syncthreads();
    }
    if (threadIdx.x == 0) g_csum2[b] = sh[0];
}

// select level 2: exact threshold key T and r = #(==T) to include
__global__ void select2_k() {
    __shared__ unsigned int sh[1024];
    __shared__ unsigned int s_chunk, s_k2;
    int t = threadIdx.x;
    const unsigned int k1 = g_k1;
    unsigned int s = g_csum2[1023 - t];
    unsigned int incl = block_incl_scan(s, sh);
    unsigned int excl = incl - s;
    if (excl < k1 && k1 <= incl) { s_chunk = 1023 - t; s_k2 = k1 - excl; }
    __syncthreads();
    const unsigned int a = s_chunk;
    const unsigned int k2 = s_k2;
    unsigned int bin = a * 1024 + 1023 - t;
    unsigned int cb = g_hist2[bin];
    __syncthreads();
    unsigned int incl2 = block_incl_scan(cb, sh);
    unsigned int excl2 = incl2 - cb;
    if (excl2 < k2 && k2 <= incl2) {
        g_T = (g_prefix12 << 20) | bin;
        g_r = k2 - excl2;
    }
}

// ---------------------------------------------------------------------------
// ties among candidates, then cutoff = r-th smallest tie index
// ---------------------------------------------------------------------------
__global__ void tie_collect_k() {
    const unsigned int T = g_T;
    unsigned int m = g_cand_cnt;
    if (m > CAND_CAP) m = CAND_CAP;
    const unsigned int stride = gridDim.x * blockDim.x;
    for (unsigned int i = blockIdx.x * blockDim.x + threadIdx.x; i < m; i += stride) {
        if (g_cand_key[i] == T) {
            unsigned int p = atomicAdd(&g_tie_cnt, 1u);
            if (p < TIE_CAP) g_tie_idx[p] = g_cand_idx[i];
        }
    }
}

__global__ void cutoff_k(int n) {
    __shared__ int s_cnt;
    unsigned int m = g_tie_cnt;
    if (m > TIE_CAP) m = TIE_CAP;
    const unsigned int r = g_r;
    if (r == 0 || m == 0) { if (threadIdx.x == 0) g_cutoff = -1; return; }
    int lo = 0, hi = n - 1;
    while (lo < hi) {
        int mid = lo + (hi - lo) / 2;
        if (threadIdx.x == 0) s_cnt = 0;
        __syncthreads();
        int c = 0;
        for (unsigned int j = threadIdx.x; j < m; j += blockDim.x)
            if (g_tie_idx[j] <= mid) c++;
        if (c) atomicAdd(&s_cnt, c);
        __syncthreads();
        if (s_cnt >= (int)r) hi = mid; else lo = mid + 1;
        __syncthreads();
    }
    if (threadIdx.x == 0) g_cutoff = lo;
}

// ---------------------------------------------------------------------------
// final: above bit + u2 -> out.
//  m=0 (incl. in-bin provisional): out = (u1 > u0)      — zero logf
//  m=1: 1+g1 > g0  <=>  a1 < e*a0, a = -log(u+eps)+eps  — two logf
// ---------------------------------------------------------------------------
__device__ __forceinline__ float out_elem(unsigned int m, float u0, float u1, int tr) {
    if (!tr) return m ? 1.0f : 0.0f;
    if (m) {
        float a0 = -logf(u0 + EPSF) + EPSF;
        float a1 = -logf(u1 + EPSF) + EPSF;
        return (a1 < EULER_F * a0) ? 1.0f : 0.0f;
    }
    return (u1 > u0) ? 1.0f : 0.0f;
}

__global__ void __launch_bounds__(256) final_k(
        const float* __restrict__ u2,
        const int* __restrict__ training,
        float* __restrict__ out, int n4) {
    const int tr = *training;
    const int stride = gridDim.x * blockDim.x;
    const int lane = threadIdx.x & 31;
    for (int i = blockIdx.x * blockDim.x + threadIdx.x; i < n4; i += stride) {
        uint4 aw = __ldg((const uint4*)g_above + (i >> 5));
        float4 a = __ldcs((const float4*)u2 + 2 * i);
        float4 b = __ldcs((const float4*)u2 + 2 * i + 1);
        float4 o;
        o.x = out_elem((aw.x >> lane) & 1u, a.x, a.y, tr);
        o.y = out_elem((aw.y >> lane) & 1u, a.z, a.w, tr);
        o.z = out_elem((aw.z >> lane) & 1u, b.x, b.y, tr);
        o.w = out_elem((aw.w >> lane) & 1u, b.z, b.w, tr);
        __stcs((float4*)out + i, o);
    }
}

// ---------------------------------------------------------------------------
// fixup2: included candidates (key > T, or == T with idx <= cutoff) get the
// exact original m=1 gumbel result.
// ---------------------------------------------------------------------------
__global__ void __launch_bounds__(256) fixup2_k(
        const float* __restrict__ u2,
        const int* __restrict__ training,
        float* __restrict__ out) {
    const unsigned int T = g_T;
    const int cutoff = g_cutoff;
    const int tr = *training;
    unsigned int m = g_cand_cnt;
    if (m > CAND_CAP) m = CAND_CAP;
    const unsigned int stride = gridDim.x * blockDim.x;
    for (unsigned int i = blockIdx.x * blockDim.x + threadIdx.x; i < m; i += stride) {
        unsigned int key = g_cand_key[i];
        if (key > T || (key == T && g_cand_idx[i] <= cutoff)) {
            int idx = g_cand_idx[i];
            float v = 1.0f;
            if (tr) {
                float2 uu = __ldg((const float2*)u2 + idx);
                v = (1.0f + gum(uu.y) > gum(uu.x)) ? 1.0f : 0.0f;
            }
            out[idx] = v;
        }
    }
}

// ---------------------------------------------------------------------------
extern "C" void kernel_launch(void* const* d_in, const int* in_sizes, int n_in,
                              void* d_out, int out_size) {
    const float* mask_logits = (const float*)d_in[0];
    const float* u1          = (const float*)d_in[1];
    const float* u2          = (const float*)d_in[2];
    const int*   kp          = (const int*)d_in[3];
    const int*   training    = (const int*)d_in[4];
    float* out = (float*)d_out;

    const int n   = in_sizes[0];
    const int n4  = n / 4;
    const int n32 = n / 32;

    reset_k<<<1024, 256>>>();
    score_hist_k<<<2048, 256>>>(mask_logits, u1, training, n4);
    select1_k<<<1, 1024>>>(kp);
    flags_k<<<2048, 256>>>(n4);
    cand_k<<<2048, 256>>>(n32);
    chunksum2_k<<<1024, 256>>>();
    select2_k<<<1, 1024>>>();
    tie_collect_k<<<256, 256>>>();
    cutoff_k<<<1, 1024>>>(n);
    final_k<<<4096, 256>>>(u2, training, out, n4);
    fixup2_k<<<1024, 256>>>(u2, training, out);
}

// round 13
// speedup vs baseline: 1.3206x; 1.0793x over previous
#include <cuda_runtime.h>
#include <cuda_bf16.h>
#include <stdint.h>

// ============================================================================
// GumbelTopK R13: fused final+hist2+collect ("finalcand").
//  A:        score -> keys32 (64MB W) + 12-bit smem hist         [192MB]
//  select1:  12-bit bin holding rank k
//  finalcand: keys (single use) + u2 -> out; in-bin elements get
//             provisional 0, feed 20-bit hist + candidate list   [256MB]
//  select2/ties/cutoff: exact threshold T, rank r, index cutoff
//  fixup2:   rewrite included candidates with exact gumbel       [small]
// m=1 gumbel test uses the (empirically exact, R12-validated) transform
// a1 < e*a0; m=0 uses u1 > u0 (0 logf).
// ============================================================================

#define N_MAX    (1u << 24)      // 4096*4096
#define H1_BINS  4096
#define H2_BINS  (1u << 20)
#define CAND_CAP (1u << 22)
#define TIE_CAP  (1u << 20)
#define CCAP     4096
#define EPSF     1e-8f
#define EULER_F  2.7182818284590452f

__device__ unsigned int g_keys[N_MAX];
__device__ unsigned int g_cand_key[CAND_CAP];
__device__ int          g_cand_idx[CAND_CAP];
__device__ int          g_tie_idx[TIE_CAP];
__device__ unsigned int g_hist1[H1_BINS];
__device__ unsigned int g_hist2[H2_BINS];
__device__ unsigned int g_csum2[1024];
__device__ unsigned int g_cand_cnt;
__device__ unsigned int g_tie_cnt;
__device__ unsigned int g_prefix12;
__device__ unsigned int g_k1;
__device__ unsigned int g_T;
__device__ unsigned int g_r;
__device__ int          g_cutoff;

__device__ __forceinline__ float gum(float u) {
    return -logf(-logf(u + EPSF) + EPSF);
}

__device__ __forceinline__ unsigned int f2key(float f) {
    unsigned int b = __float_as_uint(f);
    return (b & 0x80000000u) ? ~b : (b | 0x80000000u);
}

// ---------------------------------------------------------------------------
__global__ void reset_k() {
    int stride = gridDim.x * blockDim.x;
    for (unsigned int i = blockIdx.x * blockDim.x + threadIdx.x; i < H2_BINS; i += stride)
        g_hist2[i] = 0;
    unsigned int t = blockIdx.x * blockDim.x + threadIdx.x;
    if (t < H1_BINS) g_hist1[t] = 0;
    if (t == 0) { g_cand_cnt = 0; g_tie_cnt = 0; }
}

// ---------------------------------------------------------------------------
// pass A: score + key store + 12-bit histogram (2-way replicated smem) — R3.
// ---------------------------------------------------------------------------
__global__ void __launch_bounds__(256) score_hist_k(
        const float* __restrict__ logits,
        const float* __restrict__ u1,
        const int* __restrict__ training, int n4) {
    __shared__ unsigned int sh[2 * H1_BINS];     // 32 KB
    for (int i = threadIdx.x; i < 2 * H1_BINS; i += blockDim.x) sh[i] = 0;
    __syncthreads();
    unsigned int* mysh = sh + ((threadIdx.x >> 5) & 1) * H1_BINS;
    const int tr = *training;
    const int stride = gridDim.x * blockDim.x;
    int i = blockIdx.x * blockDim.x + threadIdx.x;
    for (; i + stride < n4; i += 2 * stride) {
        float4 l0 = __ldcs((const float4*)logits + i);
        float4 u0 = __ldcs((const float4*)u1 + i);
        float4 l1 = __ldcs((const float4*)logits + i + stride);
        float4 u1v = __ldcs((const float4*)u1 + i + stride);
        uint4 k0, k1;
        k0.x = f2key(tr ? (l0.x + gum(u0.x)) : l0.x);
        k0.y = f2key(tr ? (l0.y + gum(u0.y)) : l0.y);
        k0.z = f2key(tr ? (l0.z + gum(u0.z)) : l0.z);
        k0.w = f2key(tr ? (l0.w + gum(u0.w)) : l0.w);
        k1.x = f2key(tr ? (l1.x + gum(u1v.x)) : l1.x);
        k1.y = f2key(tr ? (l1.y + gum(u1v.y)) : l1.y);
        k1.z = f2key(tr ? (l1.z + gum(u1v.z)) : l1.z);
        k1.w = f2key(tr ? (l1.w + gum(u1v.w)) : l1.w);
        ((uint4*)g_keys)[i] = k0;
        ((uint4*)g_keys)[i + stride] = k1;
        atomicAdd(&mysh[k0.x >> 20], 1u);
        atomicAdd(&mysh[k0.y >> 20], 1u);
        atomicAdd(&mysh[k0.z >> 20], 1u);
        atomicAdd(&mysh[k0.w >> 20], 1u);
        atomicAdd(&mysh[k1.x >> 20], 1u);
        atomicAdd(&mysh[k1.y >> 20], 1u);
        atomicAdd(&mysh[k1.z >> 20], 1u);
        atomicAdd(&mysh[k1.w >> 20], 1u);
    }
    for (; i < n4; i += stride) {
        float4 l = __ldcs((const float4*)logits + i);
        float4 u = __ldcs((const float4*)u1 + i);
        uint4 kk;
        kk.x = f2key(tr ? (l.x + gum(u.x)) : l.x);
        kk.y = f2key(tr ? (l.y + gum(u.y)) : l.y);
        kk.z = f2key(tr ? (l.z + gum(u.z)) : l.z);
        kk.w = f2key(tr ? (l.w + gum(u.w)) : l.w);
        ((uint4*)g_keys)[i] = kk;
        atomicAdd(&mysh[kk.x >> 20], 1u);
        atomicAdd(&mysh[kk.y >> 20], 1u);
        atomicAdd(&mysh[kk.z >> 20], 1u);
        atomicAdd(&mysh[kk.w >> 20], 1u);
    }
    __syncthreads();
    for (int b = threadIdx.x; b < H1_BINS; b += blockDim.x) {
        unsigned int c = sh[b] + sh[b + H1_BINS];
        if (c) atomicAdd(&g_hist1[b], c);
    }
}

// ---------------------------------------------------------------------------
__device__ __forceinline__ unsigned int block_incl_scan(unsigned int v, unsigned int* sh) {
    int t = threadIdx.x;
    sh[t] = v;
    __syncthreads();
    for (int off = 1; off < blockDim.x; off <<= 1) {
        unsigned int add = (t >= off) ? sh[t - off] : 0u;
        __syncthreads();
        sh[t] += add;
        __syncthreads();
    }
    return sh[t];
}

// select level 1: 12-bit bin holding rank-k (descending)
__global__ void select1_k(const int* __restrict__ kp) {
    __shared__ unsigned int sh[1024];
    const unsigned int k = (unsigned int)(*kp);
    int t = threadIdx.x;
    unsigned int c[4], s = 0;
#pragma unroll
    for (int j = 0; j < 4; j++) { c[j] = g_hist1[4095 - (4 * t + j)]; s += c[j]; }
    unsigned int incl = block_incl_scan(s, sh);
    unsigned int excl = incl - s;
    if (excl < k && k <= incl) {
        unsigned int cum = excl;
#pragma unroll
        for (int j = 0; j < 4; j++) {
            if (cum + c[j] >= k) { g_prefix12 = 4095 - (4 * t + j); g_k1 = k - cum; break; }
            cum += c[j];
        }
    }
}

// ---------------------------------------------------------------------------
// finalcand: THE fused pass. Streams keys (single use) + u2, writes out.
//  top12 > pfx -> mask 1;  < pfx -> mask 0;
//  == pfx      -> provisional 0, hist2 atomic + staged candidate.
// m=1 gumbel: a1 < e*a0 (2 logf, R12-validated exact); m=0: u1 > u0 (0 logf).
// ---------------------------------------------------------------------------
__device__ __forceinline__ float fc_elem(
        unsigned int key, int idx, float u0, float u1,
        unsigned int pfx, int tr,
        uint2* s_buf, int* s_cnt) {
    unsigned int top = key >> 20;
    unsigned int m = (top > pfx) ? 1u : 0u;
    if (top == pfx) {
        atomicAdd(&g_hist2[key & 0xFFFFFu], 1u);
        int q = atomicAdd(s_cnt, 1);
        if (q < CCAP) s_buf[q] = make_uint2(key, (unsigned int)idx);
    }
    if (!tr) return m ? 1.0f : 0.0f;
    if (m) {
        float a0 = -logf(u0 + EPSF) + EPSF;
        float a1 = -logf(u1 + EPSF) + EPSF;
        return (a1 < EULER_F * a0) ? 1.0f : 0.0f;
    }
    return (u1 > u0) ? 1.0f : 0.0f;
}

__global__ void __launch_bounds__(256) finalcand_k(
        const float* __restrict__ u2,
        const int* __restrict__ training,
        float* __restrict__ out, int n4) {
    __shared__ uint2 s_buf[CCAP];    // 32 KB
    __shared__ int s_cnt;
    __shared__ unsigned int s_base;
    if (threadIdx.x == 0) s_cnt = 0;
    __syncthreads();
    const unsigned int pfx = g_prefix12;
    const int tr = *training;
    const int stride = gridDim.x * blockDim.x;
    int i = blockIdx.x * blockDim.x + threadIdx.x;
    for (; i + stride < n4; i += 2 * stride) {
        uint4 k0 = __ldcs((const uint4*)g_keys + i);
        float4 a0 = __ldcs((const float4*)u2 + 2 * i);
        float4 b0 = __ldcs((const float4*)u2 + 2 * i + 1);
        uint4 k1 = __ldcs((const uint4*)g_keys + i + stride);
        float4 a1 = __ldcs((const float4*)u2 + 2 * (i + stride));
        float4 b1 = __ldcs((const float4*)u2 + 2 * (i + stride) + 1);
        float4 o0, o1;
        o0.x = fc_elem(k0.x, 4 * i + 0, a0.x, a0.y, pfx, tr, s_buf, &s_cnt);
        o0.y = fc_elem(k0.y, 4 * i + 1, a0.z, a0.w, pfx, tr, s_buf, &s_cnt);
        o0.z = fc_elem(k0.z, 4 * i + 2, b0.x, b0.y, pfx, tr, s_buf, &s_cnt);
        o0.w = fc_elem(k0.w, 4 * i + 3, b0.z, b0.w, pfx, tr, s_buf, &s_cnt);
        int j = i + stride;
        o1.x = fc_elem(k1.x, 4 * j + 0, a1.x, a1.y, pfx, tr, s_buf, &s_cnt);
        o1.y = fc_elem(k1.y, 4 * j + 1, a1.z, a1.w, pfx, tr, s_buf, &s_cnt);
        o1.z = fc_elem(k1.z, 4 * j + 2, b1.x, b1.y, pfx, tr, s_buf, &s_cnt);
        o1.w = fc_elem(k1.w, 4 * j + 3, b1.z, b1.w, pfx, tr, s_buf, &s_cnt);
        __stcs((float4*)out + i, o0);
        __stcs((float4*)out + j, o1);
    }
    for (; i < n4; i += stride) {
        uint4 kk = __ldcs((const uint4*)g_keys + i);
        float4 a = __ldcs((const float4*)u2 + 2 * i);
        float4 b = __ldcs((const float4*)u2 + 2 * i + 1);
        float4 o;
        o.x = fc_elem(kk.x, 4 * i + 0, a.x, a.y, pfx, tr, s_buf, &s_cnt);
        o.y = fc_elem(kk.y, 4 * i + 1, a.z, a.w, pfx, tr, s_buf, &s_cnt);
        o.z = fc_elem(kk.z, 4 * i + 2, b.x, b.y, pfx, tr, s_buf, &s_cnt);
        o.w = fc_elem(kk.w, 4 * i + 3, b.z, b.w, pfx, tr, s_buf, &s_cnt);
        __stcs((float4*)out + i, o);
    }
    __syncthreads();
    int cnt = s_cnt;
    if (cnt > CCAP) cnt = CCAP;
    if (threadIdx.x == 0) s_base = atomicAdd(&g_cand_cnt, (unsigned int)cnt);
    __syncthreads();
    unsigned int base = s_base;
    for (int t = threadIdx.x; t < cnt; t += blockDim.x) {
        unsigned int p = base + t;
        if (p < CAND_CAP) {
            g_cand_key[p] = s_buf[t].x;
            g_cand_idx[p] = (int)s_buf[t].y;
        }
    }
}

// chunk sums of hist2 (1024 chunks of 1024 bins)
__global__ void chunksum2_k() {
    __shared__ unsigned int sh[256];
    int b = blockIdx.x;
    unsigned int s = 0;
    for (int j = threadIdx.x; j < 1024; j += 256) s += g_hist2[b * 1024 + j];
    sh[threadIdx.x] = s;
    __syncthreads();
    for (int off = 128; off > 0; off >>= 1) {
        if (threadIdx.x < off) sh[threadIdx.x] += sh[threadIdx.x + off];
        __syncthreads();
    }
    if (threadIdx.x == 0) g_csum2[b] = sh[0];
}

// select level 2: exact threshold key T and r = #(==T) to include
__global__ void select2_k() {
    __shared__ unsigned int sh[1024];
    __shared__ unsigned int s_chunk, s_k2;
    int t = threadIdx.x;
    const unsigned int k1 = g_k1;
    unsigned int s = g_csum2[1023 - t];
    unsigned int incl = block_incl_scan(s, sh);
    unsigned int excl = incl - s;
    if (excl < k1 && k1 <= incl) { s_chunk = 1023 - t; s_k2 = k1 - excl; }
    __syncthreads();
    const unsigned int a = s_chunk;
    const unsigned int k2 = s_k2;
    unsigned int bin = a * 1024 + 1023 - t;
    unsigned int cb = g_hist2[bin];
    __syncthreads();
    unsigned int incl2 = block_incl_scan(cb, sh);
    unsigned int excl2 = incl2 - cb;
    if (excl2 < k2 && k2 <= incl2) {
        g_T = (g_prefix12 << 20) | bin;
        g_r = k2 - excl2;
    }
}

// ---------------------------------------------------------------------------
// ties among candidates, then cutoff = r-th smallest tie index
// ---------------------------------------------------------------------------
__global__ void tie_collect_k() {
    const unsigned int T = g_T;
    unsigned int m = g_cand_cnt;
    if (m > CAND_CAP) m = CAND_CAP;
    const unsigned int stride = gridDim.x * blockDim.x;
    for (unsigned int i = blockIdx.x * blockDim.x + threadIdx.x; i < m; i += stride) {
        if (g_cand_key[i] == T) {
            unsigned int p = atomicAdd(&g_tie_cnt, 1u);
            if (p < TIE_CAP) g_tie_idx[p] = g_cand_idx[i];
        }
    }
}

__global__ void cutoff_k(int n) {
    __shared__ int s_cnt;
    unsigned int m = g_tie_cnt;
    if (m > TIE_CAP) m = TIE_CAP;
    const unsigned int r = g_r;
    if (r == 0 || m == 0) { if (threadIdx.x == 0) g_cutoff = -1; return; }
    int lo = 0, hi = n - 1;
    while (lo < hi) {
        int mid = lo + (hi - lo) / 2;
        if (threadIdx.x == 0) s_cnt = 0;
        __syncthreads();
        int c = 0;
        for (unsigned int j = threadIdx.x; j < m; j += blockDim.x)
            if (g_tie_idx[j] <= mid) c++;
        if (c) atomicAdd(&s_cnt, c);
        __syncthreads();
        if (s_cnt >= (int)r) hi = mid; else lo = mid + 1;
        __syncthreads();
    }
    if (threadIdx.x == 0) g_cutoff = lo;
}

// ---------------------------------------------------------------------------
// fixup2: included candidates (key > T, or == T with idx <= cutoff) get the
// exact original m=1 gumbel result.
// ---------------------------------------------------------------------------
__global__ void __launch_bounds__(256) fixup2_k(
        const float* __restrict__ u2,
        const int* __restrict__ training,
        float* __restrict__ out) {
    const unsigned int T = g_T;
    const int cutoff = g_cutoff;
    const int tr = *training;
    unsigned int m = g_cand_cnt;
    if (m > CAND_CAP) m = CAND_CAP;
    const unsigned int stride = gridDim.x * blockDim.x;
    for (unsigned int i = blockIdx.x * blockDim.x + threadIdx.x; i < m; i += stride) {
        unsigned int key = g_cand_key[i];
        if (key > T || (key == T && g_cand_idx[i] <= cutoff)) {
            int idx = g_cand_idx[i];
            float v = 1.0f;
            if (tr) {
                float2 uu = __ldg((const float2*)u2 + idx);
                float a0 = -logf(uu.x + EPSF) + EPSF;
                float a1 = -logf(uu.y + EPSF) + EPSF;
                v = (a1 < EULER_F * a0) ? 1.0f : 0.0f;
            }
            out[idx] = v;
        }
    }
}

// ---------------------------------------------------------------------------
extern "C" void kernel_launch(void* const* d_in, const int* in_sizes, int n_in,
                              void* d_out, int out_size) {
    const float* mask_logits = (const float*)d_in[0];
    const float* u1          = (const float*)d_in[1];
    const float* u2          = (const float*)d_in[2];
    const int*   kp          = (const int*)d_in[3];
    const int*   training    = (const int*)d_in[4];
    float* out = (float*)d_out;

    const int n  = in_sizes[0];
    const int n4 = n / 4;

    reset_k<<<1024, 256>>>();
    score_hist_k<<<2048, 256>>>(mask_logits, u1, training, n4);
    select1_k<<<1, 1024>>>(kp);
    finalcand_k<<<2048, 256>>>(u2, training, out, n4);
    chunksum2_k<<<1024, 256>>>();
    select2_k<<<1, 1024>>>();
    tie_collect_k<<<256, 256>>>();
    cutoff_k<<<1, 1024>>>(n);
    fixup2_k<<<1024, 256>>>(u2, training, out);
}